// round 16
// baseline (speedup 1.0000x reference)
#include <cuda_runtime.h>
#include <cuda_bf16.h>
#include <cstdint>
#include <math.h>

// Problem constants (CausalMessagePassingLayer_90237262889057)
static constexpr int B_  = 4;
static constexpr int N_  = 4096;
static constexpr int M_  = 16384;
static constexpr int EG_ = 65536;
static constexpr int EA_ = 65536;
static constexpr int D_  = 512;
static constexpr int DK_ = 64;

static constexpr int BN_ALL = B_ * N_;   // 16384
static constexpr int BM_ALL = B_ * M_;   // 65536
static constexpr int DQK    = 640;       // combined tw|q|twk width

// ---------------- scratch pool (floats; offsets 16B aligned) ----------------------
static constexpr size_t OFF_EDGE = 0;                                  // [B*M, D]
static constexpr size_t OFF_K    = OFF_EDGE + (size_t)BM_ALL * D_;     // [B*M, DK]
static constexpr size_t OFF_TWQK = OFF_K    + (size_t)BM_ALL * DK_;    // [B*N, 640]
static constexpr size_t OFF_NEW1 = OFF_TWQK + (size_t)BN_ALL * DQK;    // [B*N, D]
static constexpr size_t OFF_DEG  = OFF_NEW1 + (size_t)BN_ALL * D_;     // [B*M]
static constexpr size_t OFF_GSRC = OFF_DEG  + BM_ALL;                  // [B*EG] int
static constexpr size_t OFF_ASRC = OFF_GSRC + (size_t)B_ * EG_;        // [B*EA] int
static constexpr size_t OFF_GOFF = OFF_ASRC + (size_t)B_ * EA_;        // [BM_ALL] int
static constexpr size_t OFF_GCUR = OFF_GOFF + BM_ALL;                  // [BM_ALL] int
static constexpr size_t OFF_ACNT = OFF_GCUR + BM_ALL;                  // [BN_ALL] int
static constexpr size_t OFF_AOFF = OFF_ACNT + BN_ALL;                  // [BN_ALL] int
static constexpr size_t OFF_ACUR = OFF_AOFF + BN_ALL;                  // [BN_ALL] int
static constexpr size_t OFF_BSUM = OFF_ACUR + BN_ALL;                  // [256] int
static constexpr size_t OFF_BSM2 = OFF_BSUM + 256;                     // [64] int
static constexpr size_t OFF_WGK  = OFF_BSM2 + 64;                      // [512*64]
static constexpr size_t OFF_BGK  = OFF_WGK + (size_t)D_ * DK_;         // [64]
// packed operands
static constexpr size_t TOKP_F   = (size_t)(BN_ALL / 16) * 32 * 2 * 32 * 4;
static constexpr size_t WBIG_F   = (size_t)(D_ / 8) * 32 * 32 * 4;         // 64 nc
static constexpr size_t WQGK_F   = (size_t)(DQK / 8) * 32 * 32 * 4;        // 80 nc
static constexpr size_t OFF_TOKP = OFF_BGK + 64;
static constexpr size_t OFF_N1P  = OFF_TOKP + TOKP_F;
static constexpr size_t OFF_WQGK = OFF_N1P + TOKP_F;
static constexpr size_t OFF_WLP  = OFF_WQGK + WQGK_F;
static constexpr size_t SCRATCH_FLOATS = OFF_WLP + WBIG_F;

__device__ __align__(16) float g_scratch[SCRATCH_FLOATS];

// ---------------- mma / split helpers (PROVEN) -------------------------------------
__device__ __forceinline__ void mma16816(float* c, const uint32_t* a, const uint32_t* b)
{
    asm("mma.sync.aligned.m16n8k16.row.col.f32.bf16.bf16.f32 "
        "{%0,%1,%2,%3}, {%4,%5,%6,%7}, {%8,%9}, {%0,%1,%2,%3};"
        : "+f"(c[0]), "+f"(c[1]), "+f"(c[2]), "+f"(c[3])
        : "r"(a[0]), "r"(a[1]), "r"(a[2]), "r"(a[3]), "r"(b[0]), "r"(b[1]));
}
__device__ __forceinline__ void split2(float2 x, uint32_t& h, uint32_t& l)
{
    __nv_bfloat16 h0 = __float2bfloat16_rn(x.x);
    __nv_bfloat16 h1 = __float2bfloat16_rn(x.y);
    __nv_bfloat16 l0 = __float2bfloat16_rn(x.x - __bfloat162float(h0));
    __nv_bfloat16 l1 = __float2bfloat16_rn(x.y - __bfloat162float(h1));
    h = (uint32_t)__bfloat16_as_ushort(h0) | ((uint32_t)__bfloat16_as_ushort(h1) << 16);
    l = (uint32_t)__bfloat16_as_ushort(l0) | ((uint32_t)__bfloat16_as_ushort(l1) << 16);
}

// ---------------- merged prep: Wgk dots + bgk + init (PROVEN) -----------------------
__global__ void prep_k(const float* __restrict__ Wg, const float* __restrict__ Wk,
                       const float* __restrict__ bg, const float* __restrict__ bk,
                       float* __restrict__ Wgk, float* __restrict__ bgk,
                       float* __restrict__ deg, int* __restrict__ acnt)
{
    int blk = blockIdx.x;
    int t = threadIdx.x;
    if (blk < 128) {
        int idx = blk * 256 + t;
        int i = idx >> 6;
        int j = idx & 63;
        float s = 0.f;
        for (int c = 0; c < D_; c++)
            s = fmaf(__ldg(Wg + (size_t)i * D_ + c), __ldg(Wk + (size_t)c * DK_ + j), s);
        Wgk[idx] = s;
    } else if (blk == 128) {
        if (t < DK_) {
            float s = __ldg(bk + t);
            for (int c = 0; c < D_; c++)
                s = fmaf(__ldg(bg + c), __ldg(Wk + (size_t)c * DK_ + t), s);
            bgk[t] = s;
        }
    } else {
        int i = (blk - 129) * 256 + t;
        if (i < BM_ALL) deg[i] = 1.0f;
        if (i < BN_ALL) acnt[i] = 0;
    }
}

// ---------------- merged weight packing (PROVEN) ------------------------------------
__global__ void wpack_all(const float* __restrict__ Wg, const float* __restrict__ Wq,
                          const float* __restrict__ Wgk, const float* __restrict__ Wl,
                          uint4* __restrict__ Pqgk, uint4* __restrict__ Plp)
{
    int idx = blockIdx.x * blockDim.x + threadIdx.x;
    if (idx >= 144 * 1024) return;
    int nc   = idx >> 10;
    int ks   = (idx >> 5) & 31;
    int lane = idx & 31;
    int g = lane >> 2, t = lane & 3;
    int k = ks * 16 + 2 * t;
    const float* W; int ncols; int n; uint4* dst; int dnc;
    if (nc < 64)      { W = Wg;  ncols = D_;  n = nc * 8 + g;        dst = Pqgk; dnc = nc; }
    else if (nc < 72) { W = Wq;  ncols = DK_; n = (nc - 64) * 8 + g; dst = Pqgk; dnc = nc; }
    else if (nc < 80) { W = Wgk; ncols = DK_; n = (nc - 72) * 8 + g; dst = Pqgk; dnc = nc; }
    else              { W = Wl;  ncols = D_;  n = (nc - 80) * 8 + g; dst = Plp;  dnc = nc - 80; }
    float2 w0 = make_float2(__ldg(W + (size_t)k * ncols + n),
                            __ldg(W + (size_t)(k + 1) * ncols + n));
    float2 w1 = make_float2(__ldg(W + (size_t)(k + 8) * ncols + n),
                            __ldg(W + (size_t)(k + 9) * ncols + n));
    uint32_t b0h, b0l, b1h, b1l;
    split2(w0, b0h, b0l);
    split2(w1, b1h, b1l);
    dst[((size_t)dnc * 32 + ks) * 32 + lane] = make_uint4(b0h, b1h, b0l, b1l);
}

// ---------------- activation packing (PROVEN) ---------------------------------------
__global__ void apack_k(const float* __restrict__ A, int Mrows, uint4* __restrict__ Ap)
{
    int idx = blockIdx.x * blockDim.x + threadIdx.x;
    if (idx >= (Mrows / 16) * 1024) return;
    int rb   = idx >> 10;
    int ks   = (idx >> 5) & 31;
    int lane = idx & 31;
    int g = lane >> 2, t = lane & 3;
    int row = rb * 16 + g;
    int k = ks * 16 + 2 * t;
    const float* p0 = A + (size_t)row * D_ + k;
    const float* p1 = A + (size_t)(row + 8) * D_ + k;
    float2 x0 = *reinterpret_cast<const float2*>(p0);
    float2 x1 = *reinterpret_cast<const float2*>(p1);
    float2 x2 = *reinterpret_cast<const float2*>(p0 + 8);
    float2 x3 = *reinterpret_cast<const float2*>(p1 + 8);
    uint32_t a0h, a0l, a1h, a1l, a2h, a2l, a3h, a3l;
    split2(x0, a0h, a0l);
    split2(x1, a1h, a1l);
    split2(x2, a2h, a2l);
    split2(x3, a3h, a3l);
    size_t base = ((size_t)(rb * 32 + ks) * 2) * 32 + lane;
    Ap[base]      = make_uint4(a0h, a1h, a2h, a3h);
    Ap[base + 32] = make_uint4(a0l, a1l, a2l, a3l);
}

// ---------------- packed MMA GEMM, 128x64 block, occupancy-boosted ------------------
__global__ void __launch_bounds__(256, 3)
gemm_mma_pk(int Mrows, int Ncols,
            const uint4* __restrict__ Ap,
            const uint4* __restrict__ Bp,
            const float* __restrict__ bias,
            const float* __restrict__ resid,
            const float* __restrict__ gate,
            float* __restrict__ C)
{
    const int tid  = threadIdx.x;
    const int wid  = tid >> 5;
    const int lane = tid & 31;
    const int g    = lane >> 2;
    const int t    = lane & 3;
    const int wm   = wid >> 1;
    const int wn   = wid & 1;
    const int row0 = blockIdx.x * 128 + wm * 32;
    const int col0 = blockIdx.y * 64 + wn * 32;
    const int rb0  = row0 >> 4;
    const int nc0  = col0 >> 3;

    float c[2][4][4];
#pragma unroll
    for (int mi = 0; mi < 2; mi++)
#pragma unroll
        for (int ni = 0; ni < 4; ni++)
#pragma unroll
            for (int r = 0; r < 4; r++) c[mi][ni][r] = 0.f;

#pragma unroll 4
    for (int ks = 0; ks < 32; ks++) {
        uint32_t ah[2][4], al[2][4];
#pragma unroll
        for (int mi = 0; mi < 2; mi++) {
            size_t base = ((size_t)((rb0 + mi) * 32 + ks) * 2) * 32 + lane;
            uint4 h4 = __ldg(Ap + base);
            uint4 l4 = __ldg(Ap + base + 32);
            ah[mi][0] = h4.x; ah[mi][1] = h4.y; ah[mi][2] = h4.z; ah[mi][3] = h4.w;
            al[mi][0] = l4.x; al[mi][1] = l4.y; al[mi][2] = l4.z; al[mi][3] = l4.w;
        }
#pragma unroll
        for (int ni = 0; ni < 4; ni++) {
            uint4 b4 = __ldg(Bp + (size_t)((nc0 + ni) * 32 + ks) * 32 + lane);
            uint32_t bh[2] = { b4.x, b4.y };
            uint32_t bl[2] = { b4.z, b4.w };
#pragma unroll
            for (int mi = 0; mi < 2; mi++) {
                mma16816(c[mi][ni], ah[mi], bh);
                mma16816(c[mi][ni], ah[mi], bl);
                mma16816(c[mi][ni], al[mi], bh);
            }
        }
    }

    const float gg = gate ? tanhf(gate[0]) : 0.f;
#pragma unroll
    for (int mi = 0; mi < 2; mi++) {
        int r = row0 + mi * 16 + g;
#pragma unroll
        for (int ni = 0; ni < 4; ni++) {
            int cc = col0 + ni * 8 + 2 * t;
            float bx = 0.f, by = 0.f;
            if (bias) { bx = __ldg(bias + cc); by = __ldg(bias + cc + 1); }
            float2 v0; v0.x = c[mi][ni][0] + bx; v0.y = c[mi][ni][1] + by;
            float2 v1; v1.x = c[mi][ni][2] + bx; v1.y = c[mi][ni][3] + by;
            size_t go0 = (size_t)r * Ncols + cc;
            size_t go1 = (size_t)(r + 8) * Ncols + cc;
            if (resid) {
                float2 r0 = *reinterpret_cast<const float2*>(resid + go0);
                float2 r1 = *reinterpret_cast<const float2*>(resid + go1);
                v0.x = r0.x + gg * v0.x; v0.y = r0.y + gg * v0.y;
                v1.x = r1.x + gg * v1.x; v1.y = r1.y + gg * v1.y;
            }
            *reinterpret_cast<float2*>(C + go0) = v0;
            *reinterpret_cast<float2*>(C + go1) = v1;
        }
    }
}

// ---------------- merged counts / scans / fills (PROVEN) ----------------------------
__global__ void cnt_k(const int* __restrict__ ei_all, const int* __restrict__ aed,
                      float* __restrict__ deg, int* __restrict__ acnt)
{
    int i = blockIdx.x * blockDim.x + threadIdx.x;
    if (i >= B_ * EG_) return;
    int b = i >> 16;
    int e = i & (EG_ - 1);
    int d = __ldg(ei_all + (size_t)b * 2 * EG_ + EG_ + e);
    atomicAdd(deg + b * M_ + d, 1.0f);
    int d2 = __ldg(aed + (size_t)b * EA_ + e);
    atomicAdd(&acnt[b * N_ + d2], 1);
}

__global__ void scan_part_all(const float* __restrict__ deg, const int* __restrict__ acnt,
                              int* __restrict__ bsum, int* __restrict__ bsum2)
{
    __shared__ int sh[256];
    int t = threadIdx.x;
    if (blockIdx.x < 256) {
        int i = blockIdx.x * 256 + t;
        int v = (int)__ldg(deg + i) - 1;
        sh[t] = v; __syncthreads();
        for (int s = 128; s > 0; s >>= 1) { if (t < s) sh[t] += sh[t + s]; __syncthreads(); }
        if (t == 0) bsum[blockIdx.x] = sh[0];
    } else {
        int bi = blockIdx.x - 256;
        int i = bi * 256 + t;
        int v = __ldg(acnt + i);
        sh[t] = v; __syncthreads();
        for (int s = 128; s > 0; s >>= 1) { if (t < s) sh[t] += sh[t + s]; __syncthreads(); }
        if (t == 0) bsum2[bi] = sh[0];
    }
}
__global__ void scan_blk_all(int* __restrict__ bsum, int* __restrict__ bsum2)
{
    __shared__ int sh[256];
    int t = threadIdx.x;
    int v = bsum[t];
    sh[t] = v; __syncthreads();
    for (int off = 1; off < 256; off <<= 1) {
        int x = (t >= off) ? sh[t - off] : 0;
        __syncthreads();
        sh[t] += x;
        __syncthreads();
    }
    bsum[t] = sh[t] - v;
    __syncthreads();
    int v2 = (t < 64) ? bsum2[t] : 0;
    sh[t] = v2; __syncthreads();
    for (int off = 1; off < 64; off <<= 1) {
        int x = (t >= off) ? sh[t - off] : 0;
        __syncthreads();
        sh[t] += x;
        __syncthreads();
    }
    if (t < 64) bsum2[t] = sh[t] - v2;
}
__global__ void scan_final_all(const float* __restrict__ deg, const int* __restrict__ acnt,
                               const int* __restrict__ bsum, const int* __restrict__ bsum2,
                               int* __restrict__ goff, int* __restrict__ gcur,
                               int* __restrict__ aoff, int* __restrict__ acur)
{
    __shared__ int sh[256];
    int t = threadIdx.x;
    if (blockIdx.x < 256) {
        int i = blockIdx.x * 256 + t;
        int v = (int)__ldg(deg + i) - 1;
        sh[t] = v; __syncthreads();
        for (int off = 1; off < 256; off <<= 1) {
            int x = (t >= off) ? sh[t - off] : 0;
            __syncthreads();
            sh[t] += x;
            __syncthreads();
        }
        int o = bsum[blockIdx.x] + sh[t] - v;
        goff[i] = o; gcur[i] = o;
    } else {
        int bi = blockIdx.x - 256;
        int i = bi * 256 + t;
        int v = __ldg(acnt + i);
        sh[t] = v; __syncthreads();
        for (int off = 1; off < 256; off <<= 1) {
            int x = (t >= off) ? sh[t - off] : 0;
            __syncthreads();
            sh[t] += x;
            __syncthreads();
        }
        int o = bsum2[bi] + sh[t] - v;
        aoff[i] = o; acur[i] = o;
    }
}

__global__ void fill_k(const int* __restrict__ ei_all,
                       const int* __restrict__ aes, const int* __restrict__ aed,
                       int* __restrict__ gcur, int* __restrict__ gsrc,
                       int* __restrict__ acur, int* __restrict__ asrc)
{
    int i = blockIdx.x * blockDim.x + threadIdx.x;
    if (i >= B_ * EG_) return;
    int b = i >> 16;
    int e = i & (EG_ - 1);
    const int* ei = ei_all + (size_t)b * 2 * EG_;
    int s = __ldg(ei + e), d = __ldg(ei + EG_ + e);
    gsrc[atomicAdd(&gcur[b * M_ + d], 1)] = s;
    int s2 = __ldg(aes + (size_t)b * EA_ + e);
    int d2 = __ldg(aed + (size_t)b * EA_ + e);
    asrc[atomicAdd(&acur[b * N_ + d2], 1)] = s2;
}

// ---------------- GCN aggregation: warp per destination edge-node (PROVEN) ----------
__global__ void __launch_bounds__(256)
gcn_agg_k(const float* __restrict__ twqk, const float* __restrict__ deg,
          const int* __restrict__ t2e_all, const int* __restrict__ offs,
          const int* __restrict__ gsrc, const float* __restrict__ bg,
          const float* __restrict__ bgk,
          float* __restrict__ edge, float* __restrict__ kbuf)
{
    int w = (blockIdx.x * blockDim.x + threadIdx.x) >> 5;
    int lane = threadIdx.x & 31;
    if (w >= BM_ALL) return;
    int b = w >> 14;
    int m = w & (M_ - 1);
    float degd = __ldg(deg + w);
    float invd = rsqrtf(degd);
    float selfc = 1.0f / degd;
    int trow0 = __ldg(t2e_all + (size_t)b * M_ + m);
    const size_t rowbase = (size_t)b * N_;
    float4 acc[4];
    float2 kacc;
    {
        const float* rp = twqk + (rowbase + trow0) * DQK;
#pragma unroll
        for (int ch = 0; ch < 4; ch++) {
            int col = ch * 128 + lane * 4;
            float4 tv = *reinterpret_cast<const float4*>(rp + col);
            float4 bb = *reinterpret_cast<const float4*>(bg + col);
            acc[ch].x = bb.x + selfc * tv.x;
            acc[ch].y = bb.y + selfc * tv.y;
            acc[ch].z = bb.z + selfc * tv.z;
            acc[ch].w = bb.w + selfc * tv.w;
        }
        float2 kv = *reinterpret_cast<const float2*>(rp + 576 + 2 * lane);
        kacc.x = selfc * kv.x;
        kacc.y = selfc * kv.y;
    }
    int o0 = __ldg(offs + w);
    int cnt = (int)degd - 1;
    for (int i = 0; i < cnt; i++) {
        int s = __ldg(gsrc + o0 + i);
        float c = rsqrtf(__ldg(deg + b * M_ + s)) * invd;
        int trow = __ldg(t2e_all + (size_t)b * M_ + s);
        const float* rp = twqk + (rowbase + trow) * DQK;
#pragma unroll
        for (int ch = 0; ch < 4; ch++) {
            int col = ch * 128 + lane * 4;
            float4 tv = *reinterpret_cast<const float4*>(rp + col);
            acc[ch].x += c * tv.x; acc[ch].y += c * tv.y;
            acc[ch].z += c * tv.z; acc[ch].w += c * tv.w;
        }
        float2 kv = *reinterpret_cast<const float2*>(rp + 576 + 2 * lane);
        kacc.x += c * kv.x;
        kacc.y += c * kv.y;
    }
    float* op = edge + (size_t)w * D_;
#pragma unroll
    for (int ch = 0; ch < 4; ch++)
        *reinterpret_cast<float4*>(op + ch * 128 + lane * 4) = acc[ch];
    float2 bk2 = *reinterpret_cast<const float2*>(bgk + 2 * lane);
    float2 ko;
    ko.x = bk2.x + kacc.x;
    ko.y = bk2.y + kacc.y;
    *reinterpret_cast<float2*>(kbuf + (size_t)w * DK_ + 2 * lane) = ko;
}

// ---------------- fused attention + residual (PROVEN) -------------------------------
static constexpr int ACAP = 256;
__global__ void __launch_bounds__(256)
att_agg_k(const float* __restrict__ twqk, const float* __restrict__ bq,
          const float* __restrict__ k,
          const float* __restrict__ edge, const int* __restrict__ offs,
          const int* __restrict__ acnt, const int* __restrict__ asrc,
          const float* __restrict__ tok, const float* __restrict__ ga,
          float* __restrict__ new1)
{
    __shared__ float sdot[8][ACAP];
    __shared__ int   ssrc[8][ACAP];
    int w = (blockIdx.x * blockDim.x + threadIdx.x) >> 5;
    int wl = (threadIdx.x >> 5);
    int lane = threadIdx.x & 31;
    if (w >= BN_ALL) return;
    int b = w >> 12;
    float gg = tanhf(ga[0]);
    float2 q2 = *reinterpret_cast<const float2*>(twqk + (size_t)w * DQK + 512 + 2 * lane);
    float2 bq2 = *reinterpret_cast<const float2*>(bq + 2 * lane);
    q2.x += bq2.x;
    q2.y += bq2.y;
    int o0 = __ldg(offs + w);
    int dn = __ldg(acnt + w);
    const float* tp = tok + (size_t)w * D_;
    float* op = new1 + (size_t)w * D_;
    if (dn == 0) {
#pragma unroll
        for (int ch = 0; ch < 4; ch++) {
            int col = ch * 128 + lane * 4;
            *reinterpret_cast<float4*>(op + col) =
                *reinterpret_cast<const float4*>(tp + col);
        }
        return;
    }
    const float* kb = k + (size_t)b * M_ * DK_;
    float mx = -3.0e38f;
    for (int i = 0; i < dn; i++) {
        int s = __ldg(asrc + o0 + i);
        float2 k2 = *reinterpret_cast<const float2*>(kb + (size_t)s * DK_ + 2 * lane);
        float dot = q2.x * k2.x + q2.y * k2.y;
#pragma unroll
        for (int off = 16; off; off >>= 1) dot += __shfl_xor_sync(0xFFFFFFFFu, dot, off);
        float v = dot * 0.125f;
        if (i < ACAP && lane == 0) { sdot[wl][i] = v; ssrc[wl][i] = s; }
        mx = fmaxf(mx, v);
    }
    __syncwarp();
    float den = 0.f;
    float4 acc[4];
#pragma unroll
    for (int ch = 0; ch < 4; ch++) acc[ch] = make_float4(0.f, 0.f, 0.f, 0.f);
    const float* eb = edge + (size_t)b * M_ * D_;
    for (int i = 0; i < dn; i++) {
        float v; int s;
        if (i < ACAP) { v = sdot[wl][i]; s = ssrc[wl][i]; }
        else {
            s = __ldg(asrc + o0 + i);
            float2 k2 = *reinterpret_cast<const float2*>(kb + (size_t)s * DK_ + 2 * lane);
            float dot = q2.x * k2.x + q2.y * k2.y;
#pragma unroll
            for (int off = 16; off; off >>= 1) dot += __shfl_xor_sync(0xFFFFFFFFu, dot, off);
            v = dot * 0.125f;
        }
        float wv = __expf(v - mx);
        den += wv;
        const float* rp = eb + (size_t)s * D_;
#pragma unroll
        for (int ch = 0; ch < 4; ch++) {
            int col = ch * 128 + lane * 4;
            float4 tv = *reinterpret_cast<const float4*>(rp + col);
            acc[ch].x += wv * tv.x; acc[ch].y += wv * tv.y;
            acc[ch].z += wv * tv.z; acc[ch].w += wv * tv.w;
        }
    }
    float sc = gg / den;
#pragma unroll
    for (int ch = 0; ch < 4; ch++) {
        int col = ch * 128 + lane * 4;
        float4 tv = *reinterpret_cast<const float4*>(tp + col);
        float4 o;
        o.x = tv.x + sc * acc[ch].x;
        o.y = tv.y + sc * acc[ch].y;
        o.z = tv.z + sc * acc[ch].z;
        o.w = tv.w + sc * acc[ch].w;
        *reinterpret_cast<float4*>(op + col) = o;
    }
}

// ---------------- launch ----------------------------------------------------------
extern "C" void kernel_launch(void* const* d_in, const int* in_sizes, int n_in,
                              void* d_out, int out_size)
{
    (void)in_sizes; (void)n_in; (void)out_size;

    const float* tok = (const float*)d_in[0];
    const int*   t2e = (const int*)d_in[1];
    const int*   ei  = (const int*)d_in[2];
    const int*   aes = (const int*)d_in[3];
    const int*   aed = (const int*)d_in[4];
    const float* Wg = (const float*)d_in[5];
    const float* bg = (const float*)d_in[6];
    const float* Wk = (const float*)d_in[7];
    const float* bk = (const float*)d_in[8];
    const float* Wq = (const float*)d_in[9];
    const float* bq = (const float*)d_in[10];
    const float* Wl = (const float*)d_in[11];
    const float* bl = (const float*)d_in[12];
    const float* ga = (const float*)d_in[13];
    const float* gb = (const float*)d_in[14];
    float* out = (float*)d_out;

    float* base = nullptr;
    cudaGetSymbolAddress((void**)&base, g_scratch);

    float* edge  = base + OFF_EDGE;
    float* kbuf  = base + OFF_K;
    float* twqk  = base + OFF_TWQK;
    float* new1  = base + OFF_NEW1;
    float* deg   = base + OFF_DEG;
    int*   gsrc  = (int*)(base + OFF_GSRC);
    int*   asrc  = (int*)(base + OFF_ASRC);
    int*   goff  = (int*)(base + OFF_GOFF);
    int*   gcur  = (int*)(base + OFF_GCUR);
    int*   acnt  = (int*)(base + OFF_ACNT);
    int*   aoff  = (int*)(base + OFF_AOFF);
    int*   acur  = (int*)(base + OFF_ACUR);
    int*   bsum  = (int*)(base + OFF_BSUM);
    int*   bsum2 = (int*)(base + OFF_BSM2);
    float* wgk   = base + OFF_WGK;
    float* bgk   = base + OFF_BGK;
    uint4* tokp  = (uint4*)(base + OFF_TOKP);
    uint4* n1p   = (uint4*)(base + OFF_N1P);
    uint4* wqgkp = (uint4*)(base + OFF_WQGK);
    uint4* wlp   = (uint4*)(base + OFF_WLP);

    const int T = 256;

    // merged prep (Wgk, bgk, deg=1, acnt=0), then weight packing
    prep_k<<<449, T>>>(Wg, Wk, bg, bk, wgk, bgk, deg, acnt);
    wpack_all<<<(144 * 1024 + T - 1) / T, T>>>(Wg, Wq, wgk, Wl, wqgkp, wlp);

    // pack tok; twqk = tok @ [Wg | Wq | Wgk]
    apack_k<<<((BN_ALL / 16) * 1024 + T - 1) / T, T>>>(tok, BN_ALL, tokp);
    gemm_mma_pk<<<dim3(BN_ALL / 128, DQK / 64), 256>>>(BN_ALL, DQK, tokp, wqgkp,
                                                       nullptr, nullptr, nullptr, twqk);

    // merged counts, merged scans, merged fills
    cnt_k<<<(B_ * EG_ + T - 1) / T, T>>>(ei, aed, deg, acnt);
    scan_part_all<<<320, 256>>>(deg, acnt, bsum, bsum2);
    scan_blk_all<<<1, 256>>>(bsum, bsum2);
    scan_final_all<<<320, 256>>>(deg, acnt, bsum, bsum2, goff, gcur, aoff, acur);
    fill_k<<<(B_ * EG_ + T - 1) / T, T>>>(ei, aes, aed, gcur, gsrc, acur, asrc);

    // GCN aggregation (edge + k via linearity)
    gcn_agg_k<<<BM_ALL / 8, 256>>>(twqk, deg, t2e, goff, gsrc, bg, bgk, edge, kbuf);

    // fused attention softmax-aggregate + residual -> new1
    att_agg_k<<<BN_ALL / 8, 256>>>(twqk, bq, kbuf, edge, aoff, acnt, asrc, tok, ga, new1);

    // pack new1; out = new1 + tanh(gb) * (new1 @ Wl + bl)
    apack_k<<<((BN_ALL / 16) * 1024 + T - 1) / T, T>>>(new1, BN_ALL, n1p);
    gemm_mma_pk<<<dim3(BN_ALL / 128, D_ / 64), 256>>>(BN_ALL, D_, n1p, wlp,
                                                      bl, new1, gb, out);
}

// round 17
// speedup vs baseline: 1.0513x; 1.0513x over previous
#include <cuda_runtime.h>
#include <cuda_bf16.h>
#include <cstdint>
#include <math.h>

// Problem constants (CausalMessagePassingLayer_90237262889057)
static constexpr int B_  = 4;
static constexpr int N_  = 4096;
static constexpr int M_  = 16384;
static constexpr int EG_ = 65536;
static constexpr int EA_ = 65536;
static constexpr int D_  = 512;
static constexpr int DK_ = 64;

static constexpr int BN_ALL = B_ * N_;   // 16384
static constexpr int BM_ALL = B_ * M_;   // 65536
static constexpr int DQK    = 640;       // combined tw|q|twk width

// ---------------- scratch pool (floats; offsets 16B aligned) ----------------------
static constexpr size_t OFF_EDGE = 0;                                  // [B*M, D]
static constexpr size_t OFF_K    = OFF_EDGE + (size_t)BM_ALL * D_;     // [B*M, DK]
static constexpr size_t OFF_TWQK = OFF_K    + (size_t)BM_ALL * DK_;    // [B*N, 640]
static constexpr size_t OFF_NEW1 = OFF_TWQK + (size_t)BN_ALL * DQK;    // [B*N, D]
static constexpr size_t OFF_DEG  = OFF_NEW1 + (size_t)BN_ALL * D_;     // [B*M]
static constexpr size_t OFF_GSRC = OFF_DEG  + BM_ALL;                  // [B*EG] int
static constexpr size_t OFF_ASRC = OFF_GSRC + (size_t)B_ * EG_;        // [B*EA] int
static constexpr size_t OFF_GOFF = OFF_ASRC + (size_t)B_ * EA_;        // [BM_ALL] int
static constexpr size_t OFF_GCUR = OFF_GOFF + BM_ALL;                  // [BM_ALL] int
static constexpr size_t OFF_ACNT = OFF_GCUR + BM_ALL;                  // [BN_ALL] int
static constexpr size_t OFF_AOFF = OFF_ACNT + BN_ALL;                  // [BN_ALL] int
static constexpr size_t OFF_ACUR = OFF_AOFF + BN_ALL;                  // [BN_ALL] int
static constexpr size_t OFF_BSUM = OFF_ACUR + BN_ALL;                  // [256] int
static constexpr size_t OFF_BSM2 = OFF_BSUM + 256;                     // [64] int
static constexpr size_t OFF_WGK  = OFF_BSM2 + 64;                      // [512*64]
static constexpr size_t OFF_BGK  = OFF_WGK + (size_t)D_ * DK_;         // [64]
// packed operands
static constexpr size_t TOKP_F   = (size_t)(BN_ALL / 16) * 32 * 2 * 32 * 4;
static constexpr size_t WBIG_F   = (size_t)(D_ / 8) * 32 * 32 * 4;         // 64 nc
static constexpr size_t WQGK_F   = (size_t)(DQK / 8) * 32 * 32 * 4;        // 80 nc
static constexpr size_t OFF_TOKP = OFF_BGK + 64;
static constexpr size_t OFF_N1P  = OFF_TOKP + TOKP_F;
static constexpr size_t OFF_WQGK = OFF_N1P + TOKP_F;
static constexpr size_t OFF_WLP  = OFF_WQGK + WQGK_F;
static constexpr size_t SCRATCH_FLOATS = OFF_WLP + WBIG_F;

__device__ __align__(16) float g_scratch[SCRATCH_FLOATS];

// ---------------- mma / split helpers (PROVEN) -------------------------------------
__device__ __forceinline__ void mma16816(float* c, const uint32_t* a, const uint32_t* b)
{
    asm("mma.sync.aligned.m16n8k16.row.col.f32.bf16.bf16.f32 "
        "{%0,%1,%2,%3}, {%4,%5,%6,%7}, {%8,%9}, {%0,%1,%2,%3};"
        : "+f"(c[0]), "+f"(c[1]), "+f"(c[2]), "+f"(c[3])
        : "r"(a[0]), "r"(a[1]), "r"(a[2]), "r"(a[3]), "r"(b[0]), "r"(b[1]));
}
__device__ __forceinline__ void split2(float2 x, uint32_t& h, uint32_t& l)
{
    __nv_bfloat16 h0 = __float2bfloat16_rn(x.x);
    __nv_bfloat16 h1 = __float2bfloat16_rn(x.y);
    __nv_bfloat16 l0 = __float2bfloat16_rn(x.x - __bfloat162float(h0));
    __nv_bfloat16 l1 = __float2bfloat16_rn(x.y - __bfloat162float(h1));
    h = (uint32_t)__bfloat16_as_ushort(h0) | ((uint32_t)__bfloat16_as_ushort(h1) << 16);
    l = (uint32_t)__bfloat16_as_ushort(l0) | ((uint32_t)__bfloat16_as_ushort(l1) << 16);
}

// ---------------- merged prep: Wgk dots + bgk + init (PROVEN) -----------------------
__global__ void prep_k(const float* __restrict__ Wg, const float* __restrict__ Wk,
                       const float* __restrict__ bg, const float* __restrict__ bk,
                       float* __restrict__ Wgk, float* __restrict__ bgk,
                       float* __restrict__ deg, int* __restrict__ acnt)
{
    int blk = blockIdx.x;
    int t = threadIdx.x;
    if (blk < 128) {
        int idx = blk * 256 + t;
        int i = idx >> 6;
        int j = idx & 63;
        float s = 0.f;
        for (int c = 0; c < D_; c++)
            s = fmaf(__ldg(Wg + (size_t)i * D_ + c), __ldg(Wk + (size_t)c * DK_ + j), s);
        Wgk[idx] = s;
    } else if (blk == 128) {
        if (t < DK_) {
            float s = __ldg(bk + t);
            for (int c = 0; c < D_; c++)
                s = fmaf(__ldg(bg + c), __ldg(Wk + (size_t)c * DK_ + t), s);
            bgk[t] = s;
        }
    } else {
        int i = (blk - 129) * 256 + t;
        if (i < BM_ALL) deg[i] = 1.0f;
        if (i < BN_ALL) acnt[i] = 0;
    }
}

// ---------------- merged weight packing (PROVEN) ------------------------------------
__global__ void wpack_all(const float* __restrict__ Wg, const float* __restrict__ Wq,
                          const float* __restrict__ Wgk, const float* __restrict__ Wl,
                          uint4* __restrict__ Pqgk, uint4* __restrict__ Plp)
{
    int idx = blockIdx.x * blockDim.x + threadIdx.x;
    if (idx >= 144 * 1024) return;
    int nc   = idx >> 10;
    int ks   = (idx >> 5) & 31;
    int lane = idx & 31;
    int g = lane >> 2, t = lane & 3;
    int k = ks * 16 + 2 * t;
    const float* W; int ncols; int n; uint4* dst; int dnc;
    if (nc < 64)      { W = Wg;  ncols = D_;  n = nc * 8 + g;        dst = Pqgk; dnc = nc; }
    else if (nc < 72) { W = Wq;  ncols = DK_; n = (nc - 64) * 8 + g; dst = Pqgk; dnc = nc; }
    else if (nc < 80) { W = Wgk; ncols = DK_; n = (nc - 72) * 8 + g; dst = Pqgk; dnc = nc; }
    else              { W = Wl;  ncols = D_;  n = (nc - 80) * 8 + g; dst = Plp;  dnc = nc - 80; }
    float2 w0 = make_float2(__ldg(W + (size_t)k * ncols + n),
                            __ldg(W + (size_t)(k + 1) * ncols + n));
    float2 w1 = make_float2(__ldg(W + (size_t)(k + 8) * ncols + n),
                            __ldg(W + (size_t)(k + 9) * ncols + n));
    uint32_t b0h, b0l, b1h, b1l;
    split2(w0, b0h, b0l);
    split2(w1, b1h, b1l);
    dst[((size_t)dnc * 32 + ks) * 32 + lane] = make_uint4(b0h, b1h, b0l, b1l);
}

// ---------------- activation packing (PROVEN) ---------------------------------------
__global__ void apack_k(const float* __restrict__ A, int Mrows, uint4* __restrict__ Ap)
{
    int idx = blockIdx.x * blockDim.x + threadIdx.x;
    if (idx >= (Mrows / 16) * 1024) return;
    int rb   = idx >> 10;
    int ks   = (idx >> 5) & 31;
    int lane = idx & 31;
    int g = lane >> 2, t = lane & 3;
    int row = rb * 16 + g;
    int k = ks * 16 + 2 * t;
    const float* p0 = A + (size_t)row * D_ + k;
    const float* p1 = A + (size_t)(row + 8) * D_ + k;
    float2 x0 = *reinterpret_cast<const float2*>(p0);
    float2 x1 = *reinterpret_cast<const float2*>(p1);
    float2 x2 = *reinterpret_cast<const float2*>(p0 + 8);
    float2 x3 = *reinterpret_cast<const float2*>(p1 + 8);
    uint32_t a0h, a0l, a1h, a1l, a2h, a2l, a3h, a3l;
    split2(x0, a0h, a0l);
    split2(x1, a1h, a1l);
    split2(x2, a2h, a2l);
    split2(x3, a3h, a3l);
    size_t base = ((size_t)(rb * 32 + ks) * 2) * 32 + lane;
    Ap[base]      = make_uint4(a0h, a1h, a2h, a3h);
    Ap[base + 32] = make_uint4(a0l, a1l, a2l, a3l);
}

// ---------------- packed MMA GEMM, 128x64 block (PROVEN round-15 config) ------------
__global__ void __launch_bounds__(256)
gemm_mma_pk(int Mrows, int Ncols,
            const uint4* __restrict__ Ap,
            const uint4* __restrict__ Bp,
            const float* __restrict__ bias,
            const float* __restrict__ resid,
            const float* __restrict__ gate,
            float* __restrict__ C)
{
    const int tid  = threadIdx.x;
    const int wid  = tid >> 5;
    const int lane = tid & 31;
    const int g    = lane >> 2;
    const int t    = lane & 3;
    const int wm   = wid >> 1;
    const int wn   = wid & 1;
    const int row0 = blockIdx.x * 128 + wm * 32;
    const int col0 = blockIdx.y * 64 + wn * 32;
    const int rb0  = row0 >> 4;
    const int nc0  = col0 >> 3;

    float c[2][4][4];
#pragma unroll
    for (int mi = 0; mi < 2; mi++)
#pragma unroll
        for (int ni = 0; ni < 4; ni++)
#pragma unroll
            for (int r = 0; r < 4; r++) c[mi][ni][r] = 0.f;

#pragma unroll 4
    for (int ks = 0; ks < 32; ks++) {
        uint32_t ah[2][4], al[2][4];
#pragma unroll
        for (int mi = 0; mi < 2; mi++) {
            size_t base = ((size_t)((rb0 + mi) * 32 + ks) * 2) * 32 + lane;
            uint4 h4 = __ldg(Ap + base);
            uint4 l4 = __ldg(Ap + base + 32);
            ah[mi][0] = h4.x; ah[mi][1] = h4.y; ah[mi][2] = h4.z; ah[mi][3] = h4.w;
            al[mi][0] = l4.x; al[mi][1] = l4.y; al[mi][2] = l4.z; al[mi][3] = l4.w;
        }
#pragma unroll
        for (int ni = 0; ni < 4; ni++) {
            uint4 b4 = __ldg(Bp + (size_t)((nc0 + ni) * 32 + ks) * 32 + lane);
            uint32_t bh[2] = { b4.x, b4.y };
            uint32_t bl[2] = { b4.z, b4.w };
#pragma unroll
            for (int mi = 0; mi < 2; mi++) {
                mma16816(c[mi][ni], ah[mi], bh);
                mma16816(c[mi][ni], ah[mi], bl);
                mma16816(c[mi][ni], al[mi], bh);
            }
        }
    }

    const float gg = gate ? tanhf(gate[0]) : 0.f;
#pragma unroll
    for (int mi = 0; mi < 2; mi++) {
        int r = row0 + mi * 16 + g;
#pragma unroll
        for (int ni = 0; ni < 4; ni++) {
            int cc = col0 + ni * 8 + 2 * t;
            float bx = 0.f, by = 0.f;
            if (bias) { bx = __ldg(bias + cc); by = __ldg(bias + cc + 1); }
            float2 v0; v0.x = c[mi][ni][0] + bx; v0.y = c[mi][ni][1] + by;
            float2 v1; v1.x = c[mi][ni][2] + bx; v1.y = c[mi][ni][3] + by;
            size_t go0 = (size_t)r * Ncols + cc;
            size_t go1 = (size_t)(r + 8) * Ncols + cc;
            if (resid) {
                float2 r0 = *reinterpret_cast<const float2*>(resid + go0);
                float2 r1 = *reinterpret_cast<const float2*>(resid + go1);
                v0.x = r0.x + gg * v0.x; v0.y = r0.y + gg * v0.y;
                v1.x = r1.x + gg * v1.x; v1.y = r1.y + gg * v1.y;
            }
            *reinterpret_cast<float2*>(C + go0) = v0;
            *reinterpret_cast<float2*>(C + go1) = v1;
        }
    }
}

// ---------------- merged counts / scans / fills (PROVEN) ----------------------------
__global__ void cnt_k(const int* __restrict__ ei_all, const int* __restrict__ aed,
                      float* __restrict__ deg, int* __restrict__ acnt)
{
    int i = blockIdx.x * blockDim.x + threadIdx.x;
    if (i >= B_ * EG_) return;
    int b = i >> 16;
    int e = i & (EG_ - 1);
    int d = __ldg(ei_all + (size_t)b * 2 * EG_ + EG_ + e);
    atomicAdd(deg + b * M_ + d, 1.0f);
    int d2 = __ldg(aed + (size_t)b * EA_ + e);
    atomicAdd(&acnt[b * N_ + d2], 1);
}

__global__ void scan_part_all(const float* __restrict__ deg, const int* __restrict__ acnt,
                              int* __restrict__ bsum, int* __restrict__ bsum2)
{
    __shared__ int sh[256];
    int t = threadIdx.x;
    if (blockIdx.x < 256) {
        int i = blockIdx.x * 256 + t;
        int v = (int)__ldg(deg + i) - 1;
        sh[t] = v; __syncthreads();
        for (int s = 128; s > 0; s >>= 1) { if (t < s) sh[t] += sh[t + s]; __syncthreads(); }
        if (t == 0) bsum[blockIdx.x] = sh[0];
    } else {
        int bi = blockIdx.x - 256;
        int i = bi * 256 + t;
        int v = __ldg(acnt + i);
        sh[t] = v; __syncthreads();
        for (int s = 128; s > 0; s >>= 1) { if (t < s) sh[t] += sh[t + s]; __syncthreads(); }
        if (t == 0) bsum2[bi] = sh[0];
    }
}
__global__ void scan_blk_all(int* __restrict__ bsum, int* __restrict__ bsum2)
{
    __shared__ int sh[256];
    int t = threadIdx.x;
    int v = bsum[t];
    sh[t] = v; __syncthreads();
    for (int off = 1; off < 256; off <<= 1) {
        int x = (t >= off) ? sh[t - off] : 0;
        __syncthreads();
        sh[t] += x;
        __syncthreads();
    }
    bsum[t] = sh[t] - v;
    __syncthreads();
    int v2 = (t < 64) ? bsum2[t] : 0;
    sh[t] = v2; __syncthreads();
    for (int off = 1; off < 64; off <<= 1) {
        int x = (t >= off) ? sh[t - off] : 0;
        __syncthreads();
        sh[t] += x;
        __syncthreads();
    }
    if (t < 64) bsum2[t] = sh[t] - v2;
}
__global__ void scan_final_all(const float* __restrict__ deg, const int* __restrict__ acnt,
                               const int* __restrict__ bsum, const int* __restrict__ bsum2,
                               int* __restrict__ goff, int* __restrict__ gcur,
                               int* __restrict__ aoff, int* __restrict__ acur)
{
    __shared__ int sh[256];
    int t = threadIdx.x;
    if (blockIdx.x < 256) {
        int i = blockIdx.x * 256 + t;
        int v = (int)__ldg(deg + i) - 1;
        sh[t] = v; __syncthreads();
        for (int off = 1; off < 256; off <<= 1) {
            int x = (t >= off) ? sh[t - off] : 0;
            __syncthreads();
            sh[t] += x;
            __syncthreads();
        }
        int o = bsum[blockIdx.x] + sh[t] - v;
        goff[i] = o; gcur[i] = o;
    } else {
        int bi = blockIdx.x - 256;
        int i = bi * 256 + t;
        int v = __ldg(acnt + i);
        sh[t] = v; __syncthreads();
        for (int off = 1; off < 256; off <<= 1) {
            int x = (t >= off) ? sh[t - off] : 0;
            __syncthreads();
            sh[t] += x;
            __syncthreads();
        }
        int o = bsum2[bi] + sh[t] - v;
        aoff[i] = o; acur[i] = o;
    }
}

__global__ void fill_k(const int* __restrict__ ei_all,
                       const int* __restrict__ aes, const int* __restrict__ aed,
                       int* __restrict__ gcur, int* __restrict__ gsrc,
                       int* __restrict__ acur, int* __restrict__ asrc)
{
    int i = blockIdx.x * blockDim.x + threadIdx.x;
    if (i >= B_ * EG_) return;
    int b = i >> 16;
    int e = i & (EG_ - 1);
    const int* ei = ei_all + (size_t)b * 2 * EG_;
    int s = __ldg(ei + e), d = __ldg(ei + EG_ + e);
    gsrc[atomicAdd(&gcur[b * M_ + d], 1)] = s;
    int s2 = __ldg(aes + (size_t)b * EA_ + e);
    int d2 = __ldg(aed + (size_t)b * EA_ + e);
    asrc[atomicAdd(&acur[b * N_ + d2], 1)] = s2;
}

// ---------------- GCN aggregation: warp per destination edge-node (PROVEN) ----------
__global__ void __launch_bounds__(256)
gcn_agg_k(const float* __restrict__ twqk, const float* __restrict__ deg,
          const int* __restrict__ t2e_all, const int* __restrict__ offs,
          const int* __restrict__ gsrc, const float* __restrict__ bg,
          const float* __restrict__ bgk,
          float* __restrict__ edge, float* __restrict__ kbuf)
{
    int w = (blockIdx.x * blockDim.x + threadIdx.x) >> 5;
    int lane = threadIdx.x & 31;
    if (w >= BM_ALL) return;
    int b = w >> 14;
    int m = w & (M_ - 1);
    float degd = __ldg(deg + w);
    float invd = rsqrtf(degd);
    float selfc = 1.0f / degd;
    int trow0 = __ldg(t2e_all + (size_t)b * M_ + m);
    const size_t rowbase = (size_t)b * N_;
    float4 acc[4];
    float2 kacc;
    {
        const float* rp = twqk + (rowbase + trow0) * DQK;
#pragma unroll
        for (int ch = 0; ch < 4; ch++) {
            int col = ch * 128 + lane * 4;
            float4 tv = *reinterpret_cast<const float4*>(rp + col);
            float4 bb = *reinterpret_cast<const float4*>(bg + col);
            acc[ch].x = bb.x + selfc * tv.x;
            acc[ch].y = bb.y + selfc * tv.y;
            acc[ch].z = bb.z + selfc * tv.z;
            acc[ch].w = bb.w + selfc * tv.w;
        }
        float2 kv = *reinterpret_cast<const float2*>(rp + 576 + 2 * lane);
        kacc.x = selfc * kv.x;
        kacc.y = selfc * kv.y;
    }
    int o0 = __ldg(offs + w);
    int cnt = (int)degd - 1;
    for (int i = 0; i < cnt; i++) {
        int s = __ldg(gsrc + o0 + i);
        float c = rsqrtf(__ldg(deg + b * M_ + s)) * invd;
        int trow = __ldg(t2e_all + (size_t)b * M_ + s);
        const float* rp = twqk + (rowbase + trow) * DQK;
#pragma unroll
        for (int ch = 0; ch < 4; ch++) {
            int col = ch * 128 + lane * 4;
            float4 tv = *reinterpret_cast<const float4*>(rp + col);
            acc[ch].x += c * tv.x; acc[ch].y += c * tv.y;
            acc[ch].z += c * tv.z; acc[ch].w += c * tv.w;
        }
        float2 kv = *reinterpret_cast<const float2*>(rp + 576 + 2 * lane);
        kacc.x += c * kv.x;
        kacc.y += c * kv.y;
    }
    float* op = edge + (size_t)w * D_;
#pragma unroll
    for (int ch = 0; ch < 4; ch++)
        *reinterpret_cast<float4*>(op + ch * 128 + lane * 4) = acc[ch];
    float2 bk2 = *reinterpret_cast<const float2*>(bgk + 2 * lane);
    float2 ko;
    ko.x = bk2.x + kacc.x;
    ko.y = bk2.y + kacc.y;
    *reinterpret_cast<float2*>(kbuf + (size_t)w * DK_ + 2 * lane) = ko;
}

// ---------------- fused attention + residual (PROVEN) -------------------------------
static constexpr int ACAP = 256;
__global__ void __launch_bounds__(256)
att_agg_k(const float* __restrict__ twqk, const float* __restrict__ bq,
          const float* __restrict__ k,
          const float* __restrict__ edge, const int* __restrict__ offs,
          const int* __restrict__ acnt, const int* __restrict__ asrc,
          const float* __restrict__ tok, const float* __restrict__ ga,
          float* __restrict__ new1)
{
    __shared__ float sdot[8][ACAP];
    __shared__ int   ssrc[8][ACAP];
    int w = (blockIdx.x * blockDim.x + threadIdx.x) >> 5;
    int wl = (threadIdx.x >> 5);
    int lane = threadIdx.x & 31;
    if (w >= BN_ALL) return;
    int b = w >> 12;
    float gg = tanhf(ga[0]);
    float2 q2 = *reinterpret_cast<const float2*>(twqk + (size_t)w * DQK + 512 + 2 * lane);
    float2 bq2 = *reinterpret_cast<const float2*>(bq + 2 * lane);
    q2.x += bq2.x;
    q2.y += bq2.y;
    int o0 = __ldg(offs + w);
    int dn = __ldg(acnt + w);
    const float* tp = tok + (size_t)w * D_;
    float* op = new1 + (size_t)w * D_;
    if (dn == 0) {
#pragma unroll
        for (int ch = 0; ch < 4; ch++) {
            int col = ch * 128 + lane * 4;
            *reinterpret_cast<float4*>(op + col) =
                *reinterpret_cast<const float4*>(tp + col);
        }
        return;
    }
    const float* kb = k + (size_t)b * M_ * DK_;
    float mx = -3.0e38f;
    for (int i = 0; i < dn; i++) {
        int s = __ldg(asrc + o0 + i);
        float2 k2 = *reinterpret_cast<const float2*>(kb + (size_t)s * DK_ + 2 * lane);
        float dot = q2.x * k2.x + q2.y * k2.y;
#pragma unroll
        for (int off = 16; off; off >>= 1) dot += __shfl_xor_sync(0xFFFFFFFFu, dot, off);
        float v = dot * 0.125f;
        if (i < ACAP && lane == 0) { sdot[wl][i] = v; ssrc[wl][i] = s; }
        mx = fmaxf(mx, v);
    }
    __syncwarp();
    float den = 0.f;
    float4 acc[4];
#pragma unroll
    for (int ch = 0; ch < 4; ch++) acc[ch] = make_float4(0.f, 0.f, 0.f, 0.f);
    const float* eb = edge + (size_t)b * M_ * D_;
    for (int i = 0; i < dn; i++) {
        float v; int s;
        if (i < ACAP) { v = sdot[wl][i]; s = ssrc[wl][i]; }
        else {
            s = __ldg(asrc + o0 + i);
            float2 k2 = *reinterpret_cast<const float2*>(kb + (size_t)s * DK_ + 2 * lane);
            float dot = q2.x * k2.x + q2.y * k2.y;
#pragma unroll
            for (int off = 16; off; off >>= 1) dot += __shfl_xor_sync(0xFFFFFFFFu, dot, off);
            v = dot * 0.125f;
        }
        float wv = __expf(v - mx);
        den += wv;
        const float* rp = eb + (size_t)s * D_;
#pragma unroll
        for (int ch = 0; ch < 4; ch++) {
            int col = ch * 128 + lane * 4;
            float4 tv = *reinterpret_cast<const float4*>(rp + col);
            acc[ch].x += wv * tv.x; acc[ch].y += wv * tv.y;
            acc[ch].z += wv * tv.z; acc[ch].w += wv * tv.w;
        }
    }
    float sc = gg / den;
#pragma unroll
    for (int ch = 0; ch < 4; ch++) {
        int col = ch * 128 + lane * 4;
        float4 tv = *reinterpret_cast<const float4*>(tp + col);
        float4 o;
        o.x = tv.x + sc * acc[ch].x;
        o.y = tv.y + sc * acc[ch].y;
        o.z = tv.z + sc * acc[ch].z;
        o.w = tv.w + sc * acc[ch].w;
        *reinterpret_cast<float4*>(op + col) = o;
    }
}

// ---------------- launch ----------------------------------------------------------
extern "C" void kernel_launch(void* const* d_in, const int* in_sizes, int n_in,
                              void* d_out, int out_size)
{
    (void)in_sizes; (void)n_in; (void)out_size;

    const float* tok = (const float*)d_in[0];
    const int*   t2e = (const int*)d_in[1];
    const int*   ei  = (const int*)d_in[2];
    const int*   aes = (const int*)d_in[3];
    const int*   aed = (const int*)d_in[4];
    const float* Wg = (const float*)d_in[5];
    const float* bg = (const float*)d_in[6];
    const float* Wk = (const float*)d_in[7];
    const float* bk = (const float*)d_in[8];
    const float* Wq = (const float*)d_in[9];
    const float* bq = (const float*)d_in[10];
    const float* Wl = (const float*)d_in[11];
    const float* bl = (const float*)d_in[12];
    const float* ga = (const float*)d_in[13];
    const float* gb = (const float*)d_in[14];
    float* out = (float*)d_out;

    float* base = nullptr;
    cudaGetSymbolAddress((void**)&base, g_scratch);

    float* edge  = base + OFF_EDGE;
    float* kbuf  = base + OFF_K;
    float* twqk  = base + OFF_TWQK;
    float* new1  = base + OFF_NEW1;
    float* deg   = base + OFF_DEG;
    int*   gsrc  = (int*)(base + OFF_GSRC);
    int*   asrc  = (int*)(base + OFF_ASRC);
    int*   goff  = (int*)(base + OFF_GOFF);
    int*   gcur  = (int*)(base + OFF_GCUR);
    int*   acnt  = (int*)(base + OFF_ACNT);
    int*   aoff  = (int*)(base + OFF_AOFF);
    int*   acur  = (int*)(base + OFF_ACUR);
    int*   bsum  = (int*)(base + OFF_BSUM);
    int*   bsum2 = (int*)(base + OFF_BSM2);
    float* wgk   = base + OFF_WGK;
    float* bgk   = base + OFF_BGK;
    uint4* tokp  = (uint4*)(base + OFF_TOKP);
    uint4* n1p   = (uint4*)(base + OFF_N1P);
    uint4* wqgkp = (uint4*)(base + OFF_WQGK);
    uint4* wlp   = (uint4*)(base + OFF_WLP);

    const int T = 256;

    // one-time side stream + fork/join events (host objects; created on the
    // uncaptured correctness call, reused identically on every call)
    static cudaStream_t s1 = nullptr;
    static cudaEvent_t evF = nullptr, evJ = nullptr;
    if (!s1) {
        cudaStreamCreateWithFlags(&s1, cudaStreamNonBlocking);
        cudaEventCreateWithFlags(&evF, cudaEventDisableTiming);
        cudaEventCreateWithFlags(&evJ, cudaEventDisableTiming);
    }

    // merged prep (Wgk, bgk, deg=1, acnt=0) on main stream
    prep_k<<<449, T>>>(Wg, Wk, bg, bk, wgk, bgk, deg, acnt);

    // ---- fork: CSR chain on side stream (depends only on prep_k) ----
    cudaEventRecord(evF, 0);
    cudaStreamWaitEvent(s1, evF, 0);
    cnt_k<<<(B_ * EG_ + T - 1) / T, T, 0, s1>>>(ei, aed, deg, acnt);
    scan_part_all<<<320, 256, 0, s1>>>(deg, acnt, bsum, bsum2);
    scan_blk_all<<<1, 256, 0, s1>>>(bsum, bsum2);
    scan_final_all<<<320, 256, 0, s1>>>(deg, acnt, bsum, bsum2, goff, gcur, aoff, acur);
    fill_k<<<(B_ * EG_ + T - 1) / T, T, 0, s1>>>(ei, aes, aed, gcur, gsrc, acur, asrc);
    cudaEventRecord(evJ, s1);

    // ---- main stream: weight pack, tok pack, merged GEMM1 (independent) ----
    wpack_all<<<(144 * 1024 + T - 1) / T, T>>>(Wg, Wq, wgk, Wl, wqgkp, wlp);
    apack_k<<<((BN_ALL / 16) * 1024 + T - 1) / T, T>>>(tok, BN_ALL, tokp);
    gemm_mma_pk<<<dim3(BN_ALL / 128, DQK / 64), 256>>>(BN_ALL, DQK, tokp, wqgkp,
                                                       nullptr, nullptr, nullptr, twqk);

    // ---- join: gcn_agg needs both GEMM1 and the CSR chain ----
    cudaStreamWaitEvent(0, evJ, 0);

    // GCN aggregation (edge + k via linearity)
    gcn_agg_k<<<BM_ALL / 8, 256>>>(twqk, deg, t2e, goff, gsrc, bg, bgk, edge, kbuf);

    // fused attention softmax-aggregate + residual -> new1
    att_agg_k<<<BN_ALL / 8, 256>>>(twqk, bq, kbuf, edge, aoff, acnt, asrc, tok, ga, new1);

    // pack new1; out = new1 + tanh(gb) * (new1 @ Wl + bl)
    apack_k<<<((BN_ALL / 16) * 1024 + T - 1) / T, T>>>(new1, BN_ALL, n1p);
    gemm_mma_pk<<<dim3(BN_ALL / 128, D_ / 64), 256>>>(BN_ALL, D_, n1p, wlp,
                                                      bl, new1, gb, out);
}